// round 8
// baseline (speedup 1.0000x reference)
#include <cuda_runtime.h>
#include <cstdint>

// Furthest Point Sampling, exact-match to JAX reference.
// B=16, N=32768, M=2048. One 8-CTA cluster serves TWO batches, software
// pipelined: while batch A's candidate exchange is in flight over DSMEM,
// the cluster computes batch B's distance update / argmax / send (and vice
// versa). Per batch the structure is the proven R2 design: 4096 pts/CTA in
// f32x2-packed registers, redux.sync warp argmax, worker warp (warp 7)
// CTA-reduce + weak cluster stores + mbarrier.arrive.release, sleep-TRYWAIT,
// redundant 8-way reduce. Exchange latency is hidden behind the other
// batch's compute phase.

constexpr int NPTS = 32768;
constexpr int MOUT = 2048;
constexpr int CS   = 8;            // cluster size (CTAs per batch pair)
constexpr int PCTA = NPTS / CS;    // 4096 points per CTA per batch
constexpr int NT   = 256;          // threads per CTA
constexpr int PPT  = PCTA / NT;    // 16 points per thread per batch
constexpr int NPAIR = PPT / 2;     // 8 packed pairs
constexpr int NW   = NT / 32;      // 8 warps

struct __align__(16) ClusterShm {
    unsigned long long mbar[2];             // one mbarrier per batch (count=CS)
    unsigned long long wkey[2][NW];         // per-batch warp keys
    unsigned long long skey[2][2][CS];      // [batch][buf][src cta]
    unsigned long long sxy [2][2][CS];
    float              szv [2][2][CS];
    float cx[2][PCTA];                      // coordinate copies per batch
    float cy[2][PCTA];
    float cz[2][PCTA];
};

__device__ __forceinline__ uint32_t smem_u32(const void* p) {
    return (uint32_t)__cvta_generic_to_shared(p);
}
__device__ __forceinline__ uint32_t mapa_u32(uint32_t a, uint32_t r) {
    uint32_t out;
    asm("mapa.shared::cluster.u32 %0, %1, %2;" : "=r"(out) : "r"(a), "r"(r));
    return out;
}
// HW-sleep wait (suspendTime hint -> nap, not hot spin).
__device__ __forceinline__ void mbar_wait_sleep(uint32_t addr, uint32_t parity) {
    asm volatile(
        "{\n\t"
        ".reg .pred P;\n\t"
        "WAITLOOP%=:\n\t"
        "mbarrier.try_wait.parity.acquire.cluster.shared::cta.b64 P, [%0], %1, 0x989680;\n\t"
        "@!P bra WAITLOOP%=;\n\t"
        "}"
        :: "r"(addr), "r"(parity) : "memory");
}
__device__ __forceinline__ unsigned long long pack2(float lo, float hi) {
    unsigned long long r;
    asm("mov.b64 %0, {%1, %2};" : "=l"(r) : "f"(lo), "f"(hi));
    return r;
}
__device__ __forceinline__ void unpack2(unsigned long long v, float& lo, float& hi) {
    asm("mov.b64 {%0, %1}, %2;" : "=f"(lo), "=f"(hi) : "l"(v));
}
__device__ __forceinline__ unsigned long long addx2(unsigned long long a, unsigned long long b) {
    unsigned long long r;
    asm("add.rn.f32x2 %0, %1, %2;" : "=l"(r) : "l"(a), "l"(b));
    return r;
}
__device__ __forceinline__ unsigned long long mulx2(unsigned long long a, unsigned long long b) {
    unsigned long long r;
    asm("mul.rn.f32x2 %0, %1, %2;" : "=l"(r) : "l"(a), "l"(b));
    return r;
}

// One batch's compute + candidate send (exchange using slot buffer at the
// addresses passed in). Contains one __syncthreads (uniform).
__device__ __forceinline__ void compute_send(
    unsigned long long (&X2)[NPAIR], unsigned long long (&Y2)[NPAIR],
    unsigned long long (&Z2)[NPAIR], float (&d)[PPT],
    float lx, float ly, float lz,
    unsigned long long* wkeys,                       // s->wkey[b]
    const float* cxv, const float* cyv, const float* czv,
    uint32_t a_key, uint32_t a_xy, uint32_t a_z, uint32_t a_mb,
    int base, int lane, int wid, uint32_t rank)
{
    // --- packed distance update (exact fp32 rn, (dx^2+dy^2)+dz^2) ---
    const unsigned long long nlx2 = pack2(-lx, -lx);
    const unsigned long long nly2 = pack2(-ly, -ly);
    const unsigned long long nlz2 = pack2(-lz, -lz);
#pragma unroll
    for (int p = 0; p < NPAIR; ++p) {
        unsigned long long dx = addx2(X2[p], nlx2);
        unsigned long long dy = addx2(Y2[p], nly2);
        unsigned long long dz = addx2(Z2[p], nlz2);
        unsigned long long dd = addx2(addx2(mulx2(dx, dx), mulx2(dy, dy)),
                                      mulx2(dz, dz));
        float f0, f1; unpack2(dd, f0, f1);
        d[2 * p]     = fminf(d[2 * p],     f0);
        d[2 * p + 1] = fminf(d[2 * p + 1], f1);
    }
    // --- per-thread argmax: shallow max tree + equality mask + ffs ---
    float m8[8];
#pragma unroll
    for (int i = 0; i < 8; ++i) m8[i] = fmaxf(d[2 * i], d[2 * i + 1]);
    float m4a = fmaxf(m8[0], m8[1]), m4b = fmaxf(m8[2], m8[3]);
    float m4c = fmaxf(m8[4], m8[5]), m4d = fmaxf(m8[6], m8[7]);
    const float bv = fmaxf(fmaxf(m4a, m4b), fmaxf(m4c, m4d));
    uint32_t msk = 0;
#pragma unroll
    for (int k = 0; k < PPT; ++k) msk |= (d[k] == bv) ? (1u << k) : 0u;
    const int bk = __ffs(msk) - 1;           // smallest k -> smallest gidx
    const int bgidx = base + bk * NT;

    // --- warp argmax via redux.sync (dist >= 0: bits order-preserving) ---
    const uint32_t bvbits = __float_as_uint(bv);
    const uint32_t wval = __reduce_max_sync(0xFFFFFFFFu, bvbits);
    const uint32_t cand = (bvbits == wval) ? (uint32_t)bgidx : 0xFFFFFFFFu;
    const uint32_t widx = __reduce_min_sync(0xFFFFFFFFu, cand);
    if (lane == 0) {
        // key: max value wins; tie -> max(~idx) = min idx (first occurrence)
        wkeys[wid] = ((unsigned long long)wval << 32) |
                     (unsigned long long)(0xFFFFFFFFu - widx);
    }
    __syncthreads();

    // --- worker warp: CTA argmax + all-to-all candidate push ---
    if (wid == NW - 1) {
        unsigned long long ck = wkeys[0];    // broadcast LDS
#pragma unroll
        for (int w = 1; w < NW; ++w) {
            unsigned long long kk = wkeys[w];
            if (kk > ck) ck = kk;
        }
        const uint32_t g = 0xFFFFFFFFu - (uint32_t)ck;       // global idx
        const int lidx = (int)g - (int)rank * PCTA;           // CTA-local
        const float wx = cxv[lidx];
        const float wy = cyv[lidx];
        const float wz = czv[lidx];
        const unsigned long long cxy =
            ((unsigned long long)__float_as_uint(wy) << 32) |
            (unsigned long long)__float_as_uint(wx);
        // Lanes 0..7: weak stores then release-arrive (orders the stores
        // before the arrive's remote visibility).
        asm volatile(
            "{\n\t"
            ".reg .pred p;\n\t"
            "setp.lt.u32 p, %0, 8;\n\t"
            "@p st.shared::cluster.u64 [%1], %4;\n\t"
            "@p st.shared::cluster.u64 [%2], %5;\n\t"
            "@p st.shared::cluster.u32 [%3], %6;\n\t"
            "@p mbarrier.arrive.release.cluster.shared::cluster.b64 _, [%7];\n\t"
            "}"
            :: "r"((uint32_t)lane), "r"(a_key), "r"(a_xy), "r"(a_z),
               "l"(ck), "l"(cxy), "r"(__float_as_uint(wz)), "r"(a_mb)
            : "memory");
    }
}

__device__ __forceinline__ void recv_reduce(
    uint32_t mb, uint32_t parity,
    const unsigned long long* skey, const unsigned long long* sxy,
    const float* szv, float& lx, float& ly, float& lz)
{
    mbar_wait_sleep(mb, parity);
    unsigned long long gk = skey[0];
    int bs = 0;
#pragma unroll
    for (int c = 1; c < CS; ++c) {
        unsigned long long kk = skey[c];
        if (kk > gk) { gk = kk; bs = c; }
    }
    const unsigned long long wxy = sxy[bs];
    lx = __uint_as_float((uint32_t)wxy);
    ly = __uint_as_float((uint32_t)(wxy >> 32));
    lz = szv[bs];
}

__global__ void __launch_bounds__(NT, 1) __cluster_dims__(CS, 1, 1)
fps_kernel(const float* __restrict__ pts, float* __restrict__ out)
{
    extern __shared__ __align__(16) char shm_raw[];
    ClusterShm* s = reinterpret_cast<ClusterShm*>(shm_raw);

    const int tid = threadIdx.x;
    uint32_t rank;
    asm("mov.u32 %0, %%cluster_ctarank;" : "=r"(rank));
    const int pairidx = blockIdx.x / CS;      // cluster index: batches 2p, 2p+1

    const float* pxA = pts + (size_t)(2 * pairidx)     * 3u * NPTS;
    const float* pxB = pts + (size_t)(2 * pairidx + 1) * 3u * NPTS;
    float* obA = out + (size_t)(2 * pairidx)     * 3u * MOUT;
    float* obB = out + (size_t)(2 * pairidx + 1) * 3u * MOUT;

    const uint32_t mbA = smem_u32(&s->mbar[0]);
    const uint32_t mbB = smem_u32(&s->mbar[1]);
    if (tid == 0) {
        asm volatile("mbarrier.init.shared.b64 [%0], %1;" :: "r"(mbA), "r"(CS) : "memory");
        asm volatile("mbarrier.init.shared.b64 [%0], %1;" :: "r"(mbB), "r"(CS) : "memory");
    }

    // Load both batches' 4096-point shards into packed registers + smem copies.
    unsigned long long XA[NPAIR], YA[NPAIR], ZA[NPAIR];
    unsigned long long XB[NPAIR], YB[NPAIR], ZB[NPAIR];
    float dA[PPT], dB[PPT];
    const int base = (int)rank * PCTA + tid;
#pragma unroll
    for (int p = 0; p < NPAIR; ++p) {
        const int n0 = base + (2 * p) * NT;
        const int n1 = base + (2 * p + 1) * NT;
        const int l0 = tid + (2 * p) * NT;
        const int l1 = tid + (2 * p + 1) * NT;
        {
            float x0 = pxA[n0], x1 = pxA[n1];
            float y0 = pxA[NPTS + n0], y1 = pxA[NPTS + n1];
            float z0 = pxA[2 * NPTS + n0], z1 = pxA[2 * NPTS + n1];
            XA[p] = pack2(x0, x1); YA[p] = pack2(y0, y1); ZA[p] = pack2(z0, z1);
            s->cx[0][l0] = x0; s->cy[0][l0] = y0; s->cz[0][l0] = z0;
            s->cx[0][l1] = x1; s->cy[0][l1] = y1; s->cz[0][l1] = z1;
        }
        {
            float x0 = pxB[n0], x1 = pxB[n1];
            float y0 = pxB[NPTS + n0], y1 = pxB[NPTS + n1];
            float z0 = pxB[2 * NPTS + n0], z1 = pxB[2 * NPTS + n1];
            XB[p] = pack2(x0, x1); YB[p] = pack2(y0, y1); ZB[p] = pack2(z0, z1);
            s->cx[1][l0] = x0; s->cy[1][l0] = y0; s->cz[1][l0] = z0;
            s->cx[1][l1] = x1; s->cy[1][l1] = y1; s->cz[1][l1] = z1;
        }
        dA[2 * p] = 1e10f; dA[2 * p + 1] = 1e10f;
        dB[2 * p] = 1e10f; dB[2 * p + 1] = 1e10f;
    }
    // Selection 0 = global point 0 of each batch.
    float lxA = pxA[0], lyA = pxA[NPTS], lzA = pxA[2 * NPTS];
    float lxB = pxB[0], lyB = pxB[NPTS], lzB = pxB[2 * NPTS];

    __syncthreads();
    asm volatile("barrier.cluster.arrive.aligned;" ::: "memory");
    asm volatile("barrier.cluster.wait.aligned;"   ::: "memory");

    const bool writer = (rank == 0u) && (tid == 0);
    const int lane = tid & 31;
    const int wid  = tid >> 5;

    // Hoisted base remote addresses (buf 0); buf stride added at runtime.
    const uint32_t tr = (uint32_t)(lane & 7);
    const uint32_t akA = mapa_u32(smem_u32(&s->skey[0][0][rank]), tr);
    const uint32_t axA = mapa_u32(smem_u32(&s->sxy [0][0][rank]), tr);
    const uint32_t azA = mapa_u32(smem_u32(&s->szv [0][0][rank]), tr);
    const uint32_t akB = mapa_u32(smem_u32(&s->skey[1][0][rank]), tr);
    const uint32_t axB = mapa_u32(smem_u32(&s->sxy [1][0][rank]), tr);
    const uint32_t azB = mapa_u32(smem_u32(&s->szv [1][0][rank]), tr);
    const uint32_t amA = mapa_u32(mbA, tr);
    const uint32_t amB = mapa_u32(mbB, tr);

    // Emit selection 0.
    if (writer) {
        obA[0] = lxA; obA[MOUT] = lyA; obA[2 * MOUT] = lzA;
        obB[0] = lxB; obB[MOUT] = lyB; obB[2 * MOUT] = lzB;
    }

    // Prologue: exchange 0 for both batches (slot buffer 0).
    compute_send(XA, YA, ZA, dA, lxA, lyA, lzA, s->wkey[0],
                 s->cx[0], s->cy[0], s->cz[0],
                 akA, axA, azA, amA, base, lane, wid, rank);
    compute_send(XB, YB, ZB, dB, lxB, lyB, lzB, s->wkey[1],
                 s->cx[1], s->cy[1], s->cz[1],
                 akB, axB, azB, amB, base, lane, wid, rank);

    // Pipelined mainloop: recv exchange j, emit selection j+1, send j+1.
    for (int j = 0; j < MOUT - 2; ++j) {
        const uint32_t rb = (uint32_t)(j & 1);          // recv buf/parity
        const uint32_t sb = (uint32_t)((j + 1) & 1);    // send buf

        recv_reduce(mbA, rb, s->skey[0][rb], s->sxy[0][rb], s->szv[0][rb],
                    lxA, lyA, lzA);
        if (writer) {
            obA[j + 1] = lxA; obA[MOUT + j + 1] = lyA; obA[2 * MOUT + j + 1] = lzA;
        }
        compute_send(XA, YA, ZA, dA, lxA, lyA, lzA, s->wkey[0],
                     s->cx[0], s->cy[0], s->cz[0],
                     akA + sb * (CS * 8), axA + sb * (CS * 8), azA + sb * (CS * 4),
                     amA, base, lane, wid, rank);

        recv_reduce(mbB, rb, s->skey[1][rb], s->sxy[1][rb], s->szv[1][rb],
                    lxB, lyB, lzB);
        if (writer) {
            obB[j + 1] = lxB; obB[MOUT + j + 1] = lyB; obB[2 * MOUT + j + 1] = lzB;
        }
        compute_send(XB, YB, ZB, dB, lxB, lyB, lzB, s->wkey[1],
                     s->cx[1], s->cy[1], s->cz[1],
                     akB + sb * (CS * 8), axB + sb * (CS * 8), azB + sb * (CS * 4),
                     amB, base, lane, wid, rank);
    }

    // Epilogue: receive final exchange (k = MOUT-2, parity/buf 0) and emit.
    {
        const uint32_t rb = (uint32_t)((MOUT - 2) & 1);
        recv_reduce(mbA, rb, s->skey[0][rb], s->sxy[0][rb], s->szv[0][rb],
                    lxA, lyA, lzA);
        recv_reduce(mbB, rb, s->skey[1][rb], s->sxy[1][rb], s->szv[1][rb],
                    lxB, lyB, lzB);
        if (writer) {
            obA[MOUT - 1] = lxA; obA[2 * MOUT - 1] = lyA; obA[3 * MOUT - 1] = lzA;
            obB[MOUT - 1] = lxB; obB[2 * MOUT - 1] = lyB; obB[3 * MOUT - 1] = lzB;
        }
    }

    // No CTA exits while peers may still be touching its SMEM.
    asm volatile("barrier.cluster.arrive.aligned;" ::: "memory");
    asm volatile("barrier.cluster.wait.aligned;"   ::: "memory");
}

extern "C" void kernel_launch(void* const* d_in, const int* in_sizes, int n_in,
                              void* d_out, int out_size)
{
    (void)n_in; (void)out_size;
    const float* pts = (const float*)d_in[0];
    float* out = (float*)d_out;
    const int B = in_sizes[0] / (3 * NPTS);   // 16

    const size_t shm = sizeof(ClusterShm);    // ~97 KB
    cudaFuncSetAttribute(fps_kernel, cudaFuncAttributeMaxDynamicSharedMemorySize,
                         (int)shm);
    fps_kernel<<<(B / 2) * CS, NT, shm>>>(pts, out);
}

// round 9
// speedup vs baseline: 1.8783x; 1.8783x over previous
#include <cuda_runtime.h>
#include <cstdint>

// Furthest Point Sampling, exact-match to JAX reference.
// B=16, N=32768, M=2048. One 8-CTA cluster per batch; 4096 pts/CTA in
// f32x2-packed registers. FLAT exchange: each warp pushes its own warp-level
// candidate {key,xy,z} to ALL 8 CTAs via st.async + mbarrier complete_tx
// (data+signal, one DSMEM trip) as soon as its redux finishes. No
// __syncthreads in the main loop, no worker warp, no release-drain.
// Receivers sleep-TRYWAIT on a 1280-byte transaction barrier, then reduce
// all 64 candidates with two redux.sync ops. Double-buffered slots+barriers.

constexpr int NPTS = 32768;
constexpr int MOUT = 2048;
constexpr int CS   = 8;            // cluster size (CTAs per batch)
constexpr int PCTA = NPTS / CS;    // 4096 points per CTA
constexpr int NT   = 256;          // threads per CTA
constexpr int PPT  = PCTA / NT;    // 16 points per thread
constexpr int NPAIR = PPT / 2;     // 8 packed pairs per thread
constexpr int NW   = NT / 32;      // 8 warps
constexpr int NSLOT = CS * NW;     // 64 candidate slots
constexpr unsigned TXB = (unsigned)NSLOT * 20u;  // 1280 bytes per phase

struct __align__(16) ClusterShm {
    unsigned long long mbar[2];            // transaction barriers (dbl-buffered)
    unsigned long long skey[2][NSLOT];     // candidate keys   [buf][src]
    unsigned long long sxy [2][NSLOT];     // packed x,y
    float              szv [2][NSLOT];     // z
    float sx[PCTA];                        // coordinate copy (sender lookup)
    float sy[PCTA];
    float sz[PCTA];
};

__device__ __forceinline__ uint32_t smem_u32(const void* p) {
    return (uint32_t)__cvta_generic_to_shared(p);
}
__device__ __forceinline__ uint32_t mapa_u32(uint32_t a, uint32_t r) {
    uint32_t out;
    asm("mapa.shared::cluster.u32 %0, %1, %2;" : "=r"(out) : "r"(a), "r"(r));
    return out;
}
// HW-sleep transaction-barrier wait (suspendTime hint -> nap, not hot spin).
__device__ __forceinline__ void mbar_wait_sleep(uint32_t addr, uint32_t parity) {
    asm volatile(
        "{\n\t"
        ".reg .pred P;\n\t"
        "WAITLOOP%=:\n\t"
        "mbarrier.try_wait.parity.acquire.cta.shared::cta.b64 P, [%0], %1, 0x989680;\n\t"
        "@!P bra WAITLOOP%=;\n\t"
        "}"
        :: "r"(addr), "r"(parity) : "memory");
}
__device__ __forceinline__ unsigned long long pack2(float lo, float hi) {
    unsigned long long r;
    asm("mov.b64 %0, {%1, %2};" : "=l"(r) : "f"(lo), "f"(hi));
    return r;
}
__device__ __forceinline__ void unpack2(unsigned long long v, float& lo, float& hi) {
    asm("mov.b64 {%0, %1}, %2;" : "=f"(lo), "=f"(hi) : "l"(v));
}
__device__ __forceinline__ unsigned long long addx2(unsigned long long a, unsigned long long b) {
    unsigned long long r;
    asm("add.rn.f32x2 %0, %1, %2;" : "=l"(r) : "l"(a), "l"(b));
    return r;
}
__device__ __forceinline__ unsigned long long mulx2(unsigned long long a, unsigned long long b) {
    unsigned long long r;
    asm("mul.rn.f32x2 %0, %1, %2;" : "=l"(r) : "l"(a), "l"(b));
    return r;
}

__global__ void __launch_bounds__(NT, 1) __cluster_dims__(CS, 1, 1)
fps_kernel(const float* __restrict__ pts, float* __restrict__ out)
{
    extern __shared__ __align__(16) char shm_raw[];
    ClusterShm* s = reinterpret_cast<ClusterShm*>(shm_raw);

    const int tid = threadIdx.x;
    uint32_t rank;
    asm("mov.u32 %0, %%cluster_ctarank;" : "=r"(rank));
    const int batch = blockIdx.x / CS;

    const float* px = pts + (size_t)batch * 3u * NPTS;
    const float* py = px + NPTS;
    const float* pz = px + 2 * NPTS;
    float* ob = out + (size_t)batch * 3u * MOUT;

    const uint32_t mb0 = smem_u32(&s->mbar[0]);
    const uint32_t mb1 = smem_u32(&s->mbar[1]);
    if (tid == 0) {
        asm volatile("mbarrier.init.shared.b64 [%0], 1;" :: "r"(mb0) : "memory");
        asm volatile("mbarrier.init.shared.b64 [%0], 1;" :: "r"(mb1) : "memory");
        // Arm both buffers for their first phase.
        asm volatile("mbarrier.arrive.expect_tx.shared.b64 _, [%0], %1;"
                     :: "r"(mb0), "r"(TXB) : "memory");
        asm volatile("mbarrier.arrive.expect_tx.shared.b64 _, [%0], %1;"
                     :: "r"(mb1), "r"(TXB) : "memory");
    }

    // Load this CTA's 4096 points into packed registers (+ smem copy).
    unsigned long long X2[NPAIR], Y2[NPAIR], Z2[NPAIR];
    float d[PPT];
    const int base = (int)rank * PCTA + tid;   // global point index, k-strided
#pragma unroll
    for (int p = 0; p < NPAIR; ++p) {
        const int n0 = base + (2 * p) * NT;        // coalesced
        const int n1 = base + (2 * p + 1) * NT;
        float x0 = px[n0], x1 = px[n1];
        float y0 = py[n0], y1 = py[n1];
        float z0 = pz[n0], z1 = pz[n1];
        X2[p] = pack2(x0, x1);
        Y2[p] = pack2(y0, y1);
        Z2[p] = pack2(z0, z1);
        d[2 * p] = 1e10f; d[2 * p + 1] = 1e10f;
        const int l0 = tid + (2 * p) * NT;
        const int l1 = tid + (2 * p + 1) * NT;
        s->sx[l0] = x0; s->sy[l0] = y0; s->sz[l0] = z0;
        s->sx[l1] = x1; s->sy[l1] = y1; s->sz[l1] = z1;
    }
    // First selected point is global index 0 (CUDA FPS convention).
    float lx = px[0], ly = py[0], lz = pz[0];

    __syncthreads();
    // Barriers armed cluster-wide before any peer st.async can land.
    asm volatile("barrier.cluster.arrive.aligned;" ::: "memory");
    asm volatile("barrier.cluster.wait.aligned;"   ::: "memory");

    const bool writer = (rank == 0u) && (tid == 0);
    const int lane = tid & 31;
    const int wid  = tid >> 5;

    // Hoisted remote addresses: this warp's slot (rank*NW + wid) in target
    // CTA (lane & 7), plus the target's transaction barrier.
    const uint32_t tr = (uint32_t)(lane & 7);
    const int myslot = (int)rank * NW + wid;
    uint32_t a_key[2], a_xy[2], a_z[2], a_mb[2];
#pragma unroll
    for (int b = 0; b < 2; ++b) {
        a_key[b] = mapa_u32(smem_u32(&s->skey[b][myslot]), tr);
        a_xy[b]  = mapa_u32(smem_u32(&s->sxy [b][myslot]), tr);
        a_z[b]   = mapa_u32(smem_u32(&s->szv [b][myslot]), tr);
        a_mb[b]  = mapa_u32(b == 0 ? mb0 : mb1, tr);
    }

    for (int j = 0; j < MOUT; ++j) {
        // Emit current selection's coordinates (this IS the gathered output).
        if (writer) { ob[j] = lx; ob[MOUT + j] = ly; ob[2 * MOUT + j] = lz; }
        if (j == MOUT - 1) break;

        // --- packed distance update (exact fp32 rn, (dx^2+dy^2)+dz^2) ---
        const unsigned long long nlx2 = pack2(-lx, -lx);
        const unsigned long long nly2 = pack2(-ly, -ly);
        const unsigned long long nlz2 = pack2(-lz, -lz);
#pragma unroll
        for (int p = 0; p < NPAIR; ++p) {
            unsigned long long dx = addx2(X2[p], nlx2);
            unsigned long long dy = addx2(Y2[p], nly2);
            unsigned long long dz = addx2(Z2[p], nlz2);
            unsigned long long dd = addx2(addx2(mulx2(dx, dx), mulx2(dy, dy)),
                                          mulx2(dz, dz));
            float f0, f1; unpack2(dd, f0, f1);
            d[2 * p]     = fminf(d[2 * p],     f0);
            d[2 * p + 1] = fminf(d[2 * p + 1], f1);
        }
        // --- per-thread argmax: shallow max tree + equality mask + ffs ---
        float m8[8];
#pragma unroll
        for (int i = 0; i < 8; ++i) m8[i] = fmaxf(d[2 * i], d[2 * i + 1]);
        float m4a = fmaxf(m8[0], m8[1]), m4b = fmaxf(m8[2], m8[3]);
        float m4c = fmaxf(m8[4], m8[5]), m4d = fmaxf(m8[6], m8[7]);
        const float bv = fmaxf(fmaxf(m4a, m4b), fmaxf(m4c, m4d));
        uint32_t msk = 0;
#pragma unroll
        for (int k = 0; k < PPT; ++k) msk |= (d[k] == bv) ? (1u << k) : 0u;
        const int bk = __ffs(msk) - 1;         // smallest k -> smallest gidx
        const int bgidx = base + bk * NT;

        // --- warp argmax via redux.sync (dist >= 0: bits order-preserving) ---
        const uint32_t bvbits = __float_as_uint(bv);
        const uint32_t wval = __reduce_max_sync(0xFFFFFFFFu, bvbits);
        const uint32_t cand = (bvbits == wval) ? (uint32_t)bgidx : 0xFFFFFFFFu;
        const uint32_t widx = __reduce_min_sync(0xFFFFFFFFu, cand);

        // --- warp-winner coords via broadcast LDS into the CTA copy ---
        const int lidx = (int)widx - (int)rank * PCTA;       // CTA-local
        const float wx = s->sx[lidx];
        const float wy = s->sy[lidx];
        const float wz = s->sz[lidx];
        const unsigned long long ck =
            ((unsigned long long)wval << 32) |
            (unsigned long long)(0xFFFFFFFFu - widx);
        const unsigned long long cxy =
            ((unsigned long long)__float_as_uint(wy) << 32) |
            (unsigned long long)__float_as_uint(wx);

        const int buf = j & 1;
        const uint32_t parity = (uint32_t)(j >> 1) & 1u;

        // --- lanes 0..7: push this warp's candidate to every CTA.
        //     st.async carries complete_tx to the TARGET's barrier: data and
        //     signal in one DSMEM trip, no release-drain, no CTA barrier. ---
        asm volatile(
            "{\n\t"
            ".reg .pred p;\n\t"
            "setp.lt.u32 p, %0, 8;\n\t"
            "@p st.async.shared::cluster.mbarrier::complete_tx::bytes.b64 [%1], %4, [%7];\n\t"
            "@p st.async.shared::cluster.mbarrier::complete_tx::bytes.b64 [%2], %5, [%7];\n\t"
            "@p st.async.shared::cluster.mbarrier::complete_tx::bytes.b32 [%3], %6, [%7];\n\t"
            "}"
            :: "r"((uint32_t)lane), "r"(a_key[buf]), "r"(a_xy[buf]),
               "r"(a_z[buf]),
               "l"(ck), "l"(cxy), "r"(__float_as_uint(wz)), "r"(a_mb[buf])
            : "memory");

        // --- sleep-wait for all 1280 bytes (8 CTAs x 8 warps x 20B) ---
        mbar_wait_sleep(buf ? mb1 : mb0, parity);

        // Re-arm this buffer for phase j+2. Causally safe: any j+2 message
        // requires the sender to have completed phase j+1, which requires
        // OUR warp-0 j+1 sends, which are issued after this re-arm.
        if (tid == 0) {
            asm volatile("mbarrier.arrive.expect_tx.shared.b64 _, [%0], %1;"
                         :: "r"(buf ? mb1 : mb0), "r"(TXB) : "memory");
        }

        // --- 64-candidate reduce: 2 keys/lane + two redux ops ---
        const unsigned long long k0 = s->skey[buf][lane];
        const unsigned long long k1 = s->skey[buf][lane + 32];
        const unsigned long long m = (k0 > k1) ? k0 : k1;
        const uint32_t mv = (uint32_t)(m >> 32);
        const uint32_t gv = __reduce_max_sync(0xFFFFFFFFu, mv);
        const uint32_t inv = (mv == gv) ? (uint32_t)m : 0u;   // ~g, >0 always
        const uint32_t ginv = __reduce_max_sync(0xFFFFFFFFu, inv);
        const uint32_t g = 0xFFFFFFFFu - ginv;                // winning gidx
        // Winner's slot: src CTA = g / PCTA, src warp = (g % NT) / 32.
        const int wslot = (int)(g >> 12) * NW + (int)((g & (NT - 1)) >> 5);
        const unsigned long long wxy = s->sxy[buf][wslot];
        lx = __uint_as_float((uint32_t)wxy);
        ly = __uint_as_float((uint32_t)(wxy >> 32));
        lz = s->szv[buf][wslot];
        // Slot WAR across phases: our reads precede our own j+1 sends
        // (program order per warp); any peer j+2 store requires all 64 j+1
        // messages, hence follows every warp's reads of buffer `buf`.
    }

    // No CTA exits while peers may still be touching its SMEM.
    asm volatile("barrier.cluster.arrive.aligned;" ::: "memory");
    asm volatile("barrier.cluster.wait.aligned;"   ::: "memory");
}

extern "C" void kernel_launch(void* const* d_in, const int* in_sizes, int n_in,
                              void* d_out, int out_size)
{
    (void)n_in; (void)out_size;
    const float* pts = (const float*)d_in[0];
    float* out = (float*)d_out;
    const int B = in_sizes[0] / (3 * NPTS);   // 16

    const size_t shm = sizeof(ClusterShm);    // ~51 KB
    cudaFuncSetAttribute(fps_kernel, cudaFuncAttributeMaxDynamicSharedMemorySize,
                         (int)shm);
    fps_kernel<<<B * CS, NT, shm>>>(pts, out);
}

// round 10
// speedup vs baseline: 2.2500x; 1.1979x over previous
#include <cuda_runtime.h>
#include <cstdint>

// Furthest Point Sampling, exact-match to JAX reference.
// B=16, N=32768, M=2048. One 8-CTA cluster per batch; 4096 pts/CTA in
// f32x2-packed registers across 128 threads (32 pts/thread). FLAT exchange:
// each of the 4 warps pushes its warp-level candidate {key,xy} as ONE
// v2.b64 st.async + z as one b32 st.async (all carrying mbarrier
// complete_tx) to all 8 CTAs. Only 64 barrier-update events per phase
// (vs 192 in R8) to minimize mbarrier tx-update serialization. Receivers
// sleep-TRYWAIT on a 640-byte transaction barrier, then reduce 32
// candidates with 1 LDS + two redux.sync. Double-buffered slots+barriers.

constexpr int NPTS = 32768;
constexpr int MOUT = 2048;
constexpr int CS   = 8;            // cluster size (CTAs per batch)
constexpr int PCTA = NPTS / CS;    // 4096 points per CTA
constexpr int NT   = 128;          // threads per CTA
constexpr int PPT  = PCTA / NT;    // 32 points per thread
constexpr int NPAIR = PPT / 2;     // 16 packed pairs per thread
constexpr int NW   = NT / 32;      // 4 warps
constexpr int NSLOT = CS * NW;     // 32 candidate slots
constexpr unsigned TXB = (unsigned)NSLOT * 20u;  // 640 bytes per phase

struct __align__(16) KSlot {                // 16B: one v2.b64 st.async
    unsigned long long key;
    unsigned long long xy;
};

struct __align__(16) ClusterShm {
    unsigned long long mbar[2];            // transaction barriers (dbl-buffered)
    KSlot              skv[2][NSLOT];      // {key, packed xy} [buf][src slot]
    float              szv[2][NSLOT];      // z
    float sx[PCTA];                        // coordinate copy (sender lookup)
    float sy[PCTA];
    float sz[PCTA];
};

__device__ __forceinline__ uint32_t smem_u32(const void* p) {
    return (uint32_t)__cvta_generic_to_shared(p);
}
__device__ __forceinline__ uint32_t mapa_u32(uint32_t a, uint32_t r) {
    uint32_t out;
    asm("mapa.shared::cluster.u32 %0, %1, %2;" : "=r"(out) : "r"(a), "r"(r));
    return out;
}
// HW-sleep transaction-barrier wait (suspendTime hint -> nap, not hot spin).
__device__ __forceinline__ void mbar_wait_sleep(uint32_t addr, uint32_t parity) {
    asm volatile(
        "{\n\t"
        ".reg .pred P;\n\t"
        "WAITLOOP%=:\n\t"
        "mbarrier.try_wait.parity.acquire.cta.shared::cta.b64 P, [%0], %1, 0x989680;\n\t"
        "@!P bra WAITLOOP%=;\n\t"
        "}"
        :: "r"(addr), "r"(parity) : "memory");
}
__device__ __forceinline__ unsigned long long pack2(float lo, float hi) {
    unsigned long long r;
    asm("mov.b64 %0, {%1, %2};" : "=l"(r) : "f"(lo), "f"(hi));
    return r;
}
__device__ __forceinline__ void unpack2(unsigned long long v, float& lo, float& hi) {
    asm("mov.b64 {%0, %1}, %2;" : "=f"(lo), "=f"(hi) : "l"(v));
}
__device__ __forceinline__ unsigned long long addx2(unsigned long long a, unsigned long long b) {
    unsigned long long r;
    asm("add.rn.f32x2 %0, %1, %2;" : "=l"(r) : "l"(a), "l"(b));
    return r;
}
__device__ __forceinline__ unsigned long long mulx2(unsigned long long a, unsigned long long b) {
    unsigned long long r;
    asm("mul.rn.f32x2 %0, %1, %2;" : "=l"(r) : "l"(a), "l"(b));
    return r;
}

__global__ void __launch_bounds__(NT, 1) __cluster_dims__(CS, 1, 1)
fps_kernel(const float* __restrict__ pts, float* __restrict__ out)
{
    extern __shared__ __align__(16) char shm_raw[];
    ClusterShm* s = reinterpret_cast<ClusterShm*>(shm_raw);

    const int tid = threadIdx.x;
    uint32_t rank;
    asm("mov.u32 %0, %%cluster_ctarank;" : "=r"(rank));
    const int batch = blockIdx.x / CS;

    const float* px = pts + (size_t)batch * 3u * NPTS;
    const float* py = px + NPTS;
    const float* pz = px + 2 * NPTS;
    float* ob = out + (size_t)batch * 3u * MOUT;

    const uint32_t mb0 = smem_u32(&s->mbar[0]);
    const uint32_t mb1 = smem_u32(&s->mbar[1]);
    if (tid == 0) {
        asm volatile("mbarrier.init.shared.b64 [%0], 1;" :: "r"(mb0) : "memory");
        asm volatile("mbarrier.init.shared.b64 [%0], 1;" :: "r"(mb1) : "memory");
        // Arm both buffers for their first phase.
        asm volatile("mbarrier.arrive.expect_tx.shared.b64 _, [%0], %1;"
                     :: "r"(mb0), "r"(TXB) : "memory");
        asm volatile("mbarrier.arrive.expect_tx.shared.b64 _, [%0], %1;"
                     :: "r"(mb1), "r"(TXB) : "memory");
    }

    // Load this CTA's 4096 points into packed registers (+ smem copy).
    unsigned long long X2[NPAIR], Y2[NPAIR], Z2[NPAIR];
    float d[PPT];
    const int base = (int)rank * PCTA + tid;   // global point index, k-strided
#pragma unroll
    for (int p = 0; p < NPAIR; ++p) {
        const int n0 = base + (2 * p) * NT;        // coalesced
        const int n1 = base + (2 * p + 1) * NT;
        float x0 = px[n0], x1 = px[n1];
        float y0 = py[n0], y1 = py[n1];
        float z0 = pz[n0], z1 = pz[n1];
        X2[p] = pack2(x0, x1);
        Y2[p] = pack2(y0, y1);
        Z2[p] = pack2(z0, z1);
        d[2 * p] = 1e10f; d[2 * p + 1] = 1e10f;
        const int l0 = tid + (2 * p) * NT;
        const int l1 = tid + (2 * p + 1) * NT;
        s->sx[l0] = x0; s->sy[l0] = y0; s->sz[l0] = z0;
        s->sx[l1] = x1; s->sy[l1] = y1; s->sz[l1] = z1;
    }
    // First selected point is global index 0 (CUDA FPS convention).
    float lx = px[0], ly = py[0], lz = pz[0];

    __syncthreads();
    // Barriers armed cluster-wide before any peer st.async can land.
    asm volatile("barrier.cluster.arrive.aligned;" ::: "memory");
    asm volatile("barrier.cluster.wait.aligned;"   ::: "memory");

    const bool writer = (rank == 0u) && (tid == 0);
    const int lane = tid & 31;
    const int wid  = tid >> 5;

    // Hoisted remote addresses: this warp's slot (rank*NW + wid) in target
    // CTA (lane & 7), plus the target's transaction barrier.
    const uint32_t tr = (uint32_t)(lane & 7);
    const int myslot = (int)rank * NW + wid;
    uint32_t a_kv[2], a_z[2], a_mb[2];
#pragma unroll
    for (int b = 0; b < 2; ++b) {
        a_kv[b] = mapa_u32(smem_u32(&s->skv[b][myslot]), tr);
        a_z[b]  = mapa_u32(smem_u32(&s->szv[b][myslot]), tr);
        a_mb[b] = mapa_u32(b == 0 ? mb0 : mb1, tr);
    }

    for (int j = 0; j < MOUT; ++j) {
        // Emit current selection's coordinates (this IS the gathered output).
        if (writer) { ob[j] = lx; ob[MOUT + j] = ly; ob[2 * MOUT + j] = lz; }
        if (j == MOUT - 1) break;

        // --- packed distance update (exact fp32 rn, (dx^2+dy^2)+dz^2) ---
        const unsigned long long nlx2 = pack2(-lx, -lx);
        const unsigned long long nly2 = pack2(-ly, -ly);
        const unsigned long long nlz2 = pack2(-lz, -lz);
#pragma unroll
        for (int p = 0; p < NPAIR; ++p) {
            unsigned long long dx = addx2(X2[p], nlx2);
            unsigned long long dy = addx2(Y2[p], nly2);
            unsigned long long dz = addx2(Z2[p], nlz2);
            unsigned long long dd = addx2(addx2(mulx2(dx, dx), mulx2(dy, dy)),
                                          mulx2(dz, dz));
            float f0, f1; unpack2(dd, f0, f1);
            d[2 * p]     = fminf(d[2 * p],     f0);
            d[2 * p + 1] = fminf(d[2 * p + 1], f1);
        }
        // --- per-thread argmax: shallow max tree + equality mask + ffs ---
        float m16[16];
#pragma unroll
        for (int i = 0; i < 16; ++i) m16[i] = fmaxf(d[2 * i], d[2 * i + 1]);
        float m8[8];
#pragma unroll
        for (int i = 0; i < 8; ++i) m8[i] = fmaxf(m16[2 * i], m16[2 * i + 1]);
        float m4a = fmaxf(m8[0], m8[1]), m4b = fmaxf(m8[2], m8[3]);
        float m4c = fmaxf(m8[4], m8[5]), m4d = fmaxf(m8[6], m8[7]);
        const float bv = fmaxf(fmaxf(m4a, m4b), fmaxf(m4c, m4d));
        uint32_t msk = 0;
#pragma unroll
        for (int k = 0; k < PPT; ++k) msk |= (d[k] == bv) ? (1u << k) : 0u;
        const int bk = __ffs(msk) - 1;         // smallest k -> smallest gidx
        const int bgidx = base + bk * NT;      // gidx increases with k

        // --- warp argmax via redux.sync (dist >= 0: bits order-preserving) ---
        const uint32_t bvbits = __float_as_uint(bv);
        const uint32_t wval = __reduce_max_sync(0xFFFFFFFFu, bvbits);
        const uint32_t cand = (bvbits == wval) ? (uint32_t)bgidx : 0xFFFFFFFFu;
        const uint32_t widx = __reduce_min_sync(0xFFFFFFFFu, cand);

        // --- warp-winner coords via broadcast LDS into the CTA copy ---
        const int lidx = (int)widx - (int)rank * PCTA;       // CTA-local
        const float wx = s->sx[lidx];
        const float wy = s->sy[lidx];
        const float wz = s->sz[lidx];
        const unsigned long long ck =
            ((unsigned long long)wval << 32) |
            (unsigned long long)(0xFFFFFFFFu - widx);
        const unsigned long long cxy =
            ((unsigned long long)__float_as_uint(wy) << 32) |
            (unsigned long long)__float_as_uint(wx);

        const int buf = j & 1;
        const uint32_t parity = (uint32_t)(j >> 1) & 1u;

        // --- lanes 0..7: push this warp's candidate to every CTA.
        //     v2.b64 {key,xy} + b32 z, each with complete_tx at the TARGET's
        //     barrier: 2 update events per sender-target, 64 per barrier. ---
        asm volatile(
            "{\n\t"
            ".reg .pred p;\n\t"
            "setp.lt.u32 p, %0, 8;\n\t"
            "@p st.async.shared::cluster.mbarrier::complete_tx::bytes.v2.b64 [%1], {%3, %4}, [%5];\n\t"
            "@p st.async.shared::cluster.mbarrier::complete_tx::bytes.b32 [%2], %6, [%5];\n\t"
            "}"
            :: "r"((uint32_t)lane), "r"(a_kv[buf]), "r"(a_z[buf]),
               "l"(ck), "l"(cxy), "r"(a_mb[buf]), "r"(__float_as_uint(wz))
            : "memory");

        // --- sleep-wait for all 640 bytes (8 CTAs x 4 warps x 20B) ---
        mbar_wait_sleep(buf ? mb1 : mb0, parity);

        // Re-arm this buffer for phase j+2. Causally safe: any j+2 message
        // requires the sender to have completed phase j+1, which requires
        // OUR j+1 sends, which are issued after this re-arm.
        if (tid == 0) {
            asm volatile("mbarrier.arrive.expect_tx.shared.b64 _, [%0], %1;"
                         :: "r"(buf ? mb1 : mb0), "r"(TXB) : "memory");
        }

        // --- 32-candidate reduce: 1 key/lane + two redux ops ---
        const unsigned long long m = s->skv[buf][lane].key;
        const uint32_t mv = (uint32_t)(m >> 32);
        const uint32_t gv = __reduce_max_sync(0xFFFFFFFFu, mv);
        const uint32_t inv = (mv == gv) ? (uint32_t)m : 0u;   // ~g, >0 always
        const uint32_t ginv = __reduce_max_sync(0xFFFFFFFFu, inv);
        const uint32_t g = 0xFFFFFFFFu - ginv;                // winning gidx
        // Winner's slot: src CTA = g / PCTA, src warp = (g % NT) / 32.
        const int wslot = (int)(g >> 12) * NW + (int)((g & (NT - 1)) >> 5);
        const unsigned long long wxy = s->skv[buf][wslot].xy;
        lx = __uint_as_float((uint32_t)wxy);
        ly = __uint_as_float((uint32_t)(wxy >> 32));
        lz = s->szv[buf][wslot];
        // Slot WAR across phases: our reads precede our own j+1 sends
        // (program order per warp); any peer j+2 store requires all 32 j+1
        // messages, hence follows every warp's reads of buffer `buf`.
    }

    // No CTA exits while peers may still be touching its SMEM.
    asm volatile("barrier.cluster.arrive.aligned;" ::: "memory");
    asm volatile("barrier.cluster.wait.aligned;"   ::: "memory");
}

extern "C" void kernel_launch(void* const* d_in, const int* in_sizes, int n_in,
                              void* d_out, int out_size)
{
    (void)n_in; (void)out_size;
    const float* pts = (const float*)d_in[0];
    float* out = (float*)d_out;
    const int B = in_sizes[0] / (3 * NPTS);   // 16

    const size_t shm = sizeof(ClusterShm);    // ~50 KB
    cudaFuncSetAttribute(fps_kernel, cudaFuncAttributeMaxDynamicSharedMemorySize,
                         (int)shm);
    fps_kernel<<<B * CS, NT, shm>>>(pts, out);
}